// round 7
// baseline (speedup 1.0000x reference)
#include <cuda_runtime.h>
#include <cuda_bf16.h>
#include <cstdint>

#define NB 16384
#define ND 5000
#define NJ 192
#define KENC_PAD 5056          // 158 * 32
#define NDEC_PAD 5120          // 40 * 128
#define DEC_SCALE 0.0159f
#define CARD_B 24
#define CARD_C 10
#define NBIN (CARD_B * CARD_B + CARD_C * CARD_C)   // 676

// ---------------- device-global scratch --------------------------------------
__device__ __align__(16) float         g_H[NB * NJ];
__device__ __align__(16) __nv_bfloat16 g_Hhi[NB * NJ];
__device__ __align__(16) __nv_bfloat16 g_Hlo[NB * NJ];
__device__ __align__(16) __nv_bfloat16 g_exprHi[(size_t)NB * KENC_PAD];
__device__ __align__(16) __nv_bfloat16 g_exprLo[(size_t)NB * KENC_PAD];
__device__ __align__(16) __nv_bfloat16 g_WencHi[NJ * KENC_PAD];
__device__ __align__(16) __nv_bfloat16 g_WencLo[NJ * KENC_PAD];
__device__ __align__(16) __nv_bfloat16 g_WdTHi[NDEC_PAD * NJ];
__device__ __align__(16) float         g_MbT[CARD_B * CARD_B * 4096];
__device__ __align__(16) __nv_bfloat16 g_WdTLo[NDEC_PAD * NJ];
__device__ __align__(16) float         g_McT[CARD_C * CARD_C * 4096];
__device__ int g_off[NBIN + 1];
__device__ int g_rows[2 * NB];

// ---------------- PTX helpers -------------------------------------------------
__device__ __forceinline__ uint32_t s2u(const void* p) {
    return (uint32_t)__cvta_generic_to_shared(p);
}
__device__ __forceinline__ void cp16(uint32_t dst, const void* src) {
    asm volatile("cp.async.cg.shared.global [%0], [%1], 16;" :: "r"(dst), "l"(src));
}
__device__ __forceinline__ void cp_commit() {
    asm volatile("cp.async.commit_group;" ::: "memory");
}
template <int N> __device__ __forceinline__ void cp_wait() {
    asm volatile("cp.async.wait_group %0;" :: "n"(N) : "memory");
}
__device__ __forceinline__ void ldsm4(uint32_t* r, uint32_t a) {
    asm volatile("ldmatrix.sync.aligned.m8n8.x4.shared.b16 {%0,%1,%2,%3}, [%4];"
                 : "=r"(r[0]), "=r"(r[1]), "=r"(r[2]), "=r"(r[3]) : "r"(a));
}
__device__ __forceinline__ void mma16816(float* c, const uint32_t* a, const uint32_t* b) {
    asm volatile("mma.sync.aligned.m16n8k16.row.col.f32.bf16.bf16.f32 "
                 "{%0,%1,%2,%3},{%4,%5,%6,%7},{%8,%9},{%0,%1,%2,%3};"
                 : "+f"(c[0]), "+f"(c[1]), "+f"(c[2]), "+f"(c[3])
                 : "r"(a[0]), "r"(a[1]), "r"(a[2]), "r"(a[3]), "r"(b[0]), "r"(b[1]));
}
__device__ __forceinline__ void split2(float f0, float f1, uint32_t& h, uint32_t& l) {
    __nv_bfloat16 h0 = __float2bfloat16_rn(f0);
    __nv_bfloat16 h1 = __float2bfloat16_rn(f1);
    __nv_bfloat16 l0 = __float2bfloat16_rn(f0 - __bfloat162float(h0));
    __nv_bfloat16 l1 = __float2bfloat16_rn(f1 - __bfloat162float(h1));
    h = (uint32_t)__bfloat16_as_ushort(h0) | ((uint32_t)__bfloat16_as_ushort(h1) << 16);
    l = (uint32_t)__bfloat16_as_ushort(l0) | ((uint32_t)__bfloat16_as_ushort(l1) << 16);
}
__device__ __forceinline__ void store_split(size_t i, float v) {
    __nv_bfloat16 h = __float2bfloat16_rn(v);
    g_Hhi[i] = h;
    g_Hlo[i] = __float2bfloat16_rn(v - __bfloat162float(h));
}

// ---------------- pack kernels ------------------------------------------------
__global__ void pack_enc_kernel(const float* __restrict__ Wb,
                                const float* __restrict__ Web,
                                const float* __restrict__ Wec) {
    int idx = blockIdx.x * blockDim.x + threadIdx.x;
    int j = idx / KENC_PAD, d = idx - j * KENC_PAD;
    float v = 0.f;
    if (d < ND) {
        if (j < 64)       v = Wb[j * ND + d];
        else if (j < 128) v = Web[(j - 64) * ND + d];
        else              v = Wec[(j - 128) * ND + d];
    }
    __nv_bfloat16 h = __float2bfloat16_rn(v);
    g_WencHi[idx] = h;
    g_WencLo[idx] = __float2bfloat16_rn(v - __bfloat162float(h));
}
__global__ void pack_dec_kernel(const float* __restrict__ Wb,
                                const float* __restrict__ Wdb,
                                const float* __restrict__ Wdc) {
    int idx = blockIdx.x * blockDim.x + threadIdx.x;
    int n = idx / NJ, j = idx - n * NJ;
    float v = 0.f;
    if (n < ND) {
        if (j < 64)       v = Wb[j * ND + n];
        else if (j < 128) v = Wdb[n * 64 + (j - 64)];
        else              v = Wdc[n * 64 + (j - 128)];
    }
    __nv_bfloat16 h = __float2bfloat16_rn(v);
    g_WdTHi[idx] = h;
    g_WdTLo[idx] = __float2bfloat16_rn(v - __bfloat162float(h));
}

// ---------------- split expr -> bf16 hi/lo (padded K) -------------------------
__global__ __launch_bounds__(256) void split_expr_kernel(const float* __restrict__ A) {
    size_t e = ((size_t)blockIdx.x * 256 + threadIdx.x) * 8;   // 8 elems/thread
    int row = (int)(e / KENC_PAD);
    int col = (int)(e - (size_t)row * KENC_PAD);
    uint32_t h[4], l[4];
    if (col + 8 <= ND) {
        const float4* p = (const float4*)(A + (size_t)row * ND + col);
        float4 a = p[0], b = p[1];
        split2(a.x, a.y, h[0], l[0]);
        split2(a.z, a.w, h[1], l[1]);
        split2(b.x, b.y, h[2], l[2]);
        split2(b.z, b.w, h[3], l[3]);
    } else {
#pragma unroll
        for (int i = 0; i < 4; i++) {
            float v0 = (col + 2 * i < ND)     ? A[(size_t)row * ND + col + 2 * i]     : 0.f;
            float v1 = (col + 2 * i + 1 < ND) ? A[(size_t)row * ND + col + 2 * i + 1] : 0.f;
            split2(v0, v1, h[i], l[i]);
        }
    }
    *(uint4*)(g_exprHi + e) = make_uint4(h[0], h[1], h[2], h[3]);
    *(uint4*)(g_exprLo + e) = make_uint4(l[0], l[1], l[2], l[3]);
}

// ---------------- composite: MT[pair][l][m] = scale * (W[t] @ W[s])[m,l] -----
__global__ __launch_bounds__(256) void composite_kernel(const float* __restrict__ Whb,
                                                        const float* __restrict__ Whc) {
    __shared__ float sT[4096], sS[4096];
    int pair = blockIdx.x;
    const float *Wt, *Ws;
    float* out;
    if (pair < CARD_B * CARD_B) {
        Wt = Whb + (size_t)(pair / CARD_B) * 4096;
        Ws = Whb + (size_t)(pair % CARD_B) * 4096;
        out = g_MbT + (size_t)pair * 4096;
    } else {
        int p = pair - CARD_B * CARD_B;
        Wt = Whc + (size_t)(p / CARD_C) * 4096;
        Ws = Whc + (size_t)(p % CARD_C) * 4096;
        out = g_McT + (size_t)p * 4096;
    }
    int tid = threadIdx.x;
    for (int i = tid; i < 4096; i += 256) { sT[i] = Wt[i]; sS[i] = Ws[i]; }
    __syncthreads();
    int m = tid >> 2, n0 = (tid & 3) * 16;
    float c[16];
#pragma unroll
    for (int j = 0; j < 16; j++) c[j] = 0.f;
    for (int l = 0; l < 64; l++) {
        float a = sT[m * 64 + l];
#pragma unroll
        for (int j = 0; j < 16; j++) c[j] = fmaf(a, sS[l * 64 + n0 + j], c[j]);
    }
#pragma unroll
    for (int j = 0; j < 16; j++) out[(n0 + j) * 64 + m] = c[j] * DEC_SCALE;
}

// ---------------- bucketing: single-CTA fused count/scan/scatter --------------
__global__ __launch_bounds__(1024) void bucket_all_kernel(const int* __restrict__ sb,
                                                          const int* __restrict__ tb,
                                                          const int* __restrict__ sc,
                                                          const int* __restrict__ tc) {
    __shared__ int scnt[NBIN];
    __shared__ int scur[NBIN];
    const int tid = threadIdx.x;
    for (int i = tid; i < NBIN; i += 1024) scnt[i] = 0;
    __syncthreads();
    for (int row = tid; row < NB; row += 1024) {
        atomicAdd(&scnt[tb[row] * CARD_B + sb[row]], 1);
        atomicAdd(&scnt[CARD_B * CARD_B + tc[row] * CARD_C + sc[row]], 1);
    }
    __syncthreads();
    if (tid == 0) {
        int acc = 0;
        for (int i = 0; i < NBIN; i++) {
            scur[i] = acc;
            g_off[i] = acc;
            acc += scnt[i];
        }
        g_off[NBIN] = acc;
    }
    __syncthreads();
    for (int row = tid; row < NB; row += 1024) {
        int pb = tb[row] * CARD_B + sb[row];
        int pc = CARD_B * CARD_B + tc[row] * CARD_C + sc[row];
        g_rows[atomicAdd(&scur[pb], 1)] = row;
        g_rows[atomicAdd(&scur[pc], 1)] = row;
    }
}

// ---------------- encode ------------------------------------------------------
// 512 threads, 16 warps 4Mx4N (warp 32x48). Tile 128x192, BK=32.
// 4-stage pure cp.async pipeline. Stage bytes (row stride 40 halves = 80B):
//   Ahi@0 (10240) | Alo@10240 | Bhi@20480 (15360) | Blo@35840 ; 51200/stage.
#define ENC_STAGES 4
#define ENC_SMEM_BYTES (ENC_STAGES * 51200)
__global__ __launch_bounds__(512, 1) void encode_kernel() {
    extern __shared__ __nv_bfloat16 sm[];
    const uint32_t sbase = s2u(sm);
    const int tid = threadIdx.x, wid = tid >> 5, lane = tid & 31;
    const int row0 = blockIdx.x * 128;
    const int wm = (wid & 3) * 32, wn = (wid >> 2) * 48;

    float acc[2][6][4];
#pragma unroll
    for (int i = 0; i < 2; i++)
#pragma unroll
        for (int j = 0; j < 6; j++)
#pragma unroll
            for (int k = 0; k < 4; k++) acc[i][j][k] = 0.f;

    const int rt = tid >> 2, ct = tid & 3;
    auto cp_stage = [&](int kt, int s) {
        const int k0 = kt * 32;
        uint32_t base = sbase + (uint32_t)s * 51200u;
        {   // A: 128 rows x 4 chunks (hi+lo)
            uint32_t o = (uint32_t)(rt * 40 + ct * 8) * 2u;
            size_t g = (size_t)(row0 + rt) * KENC_PAD + k0 + ct * 8;
            cp16(base + o,          g_exprHi + g);
            cp16(base + 10240u + o, g_exprLo + g);
        }
        {   // B chunks 0..511
            uint32_t o = (uint32_t)(rt * 40 + ct * 8) * 2u;
            size_t g = (size_t)rt * KENC_PAD + k0 + ct * 8;
            cp16(base + 20480u + o, g_WencHi + g);
            cp16(base + 35840u + o, g_WencLo + g);
        }
        if (tid < 256) {   // B chunks 512..767
            int idx = tid + 512;
            int n = idx >> 2, c = idx & 3;
            uint32_t o = (uint32_t)(n * 40 + c * 8) * 2u;
            size_t g = (size_t)n * KENC_PAD + k0 + c * 8;
            cp16(base + 20480u + o, g_WencHi + g);
            cp16(base + 35840u + o, g_WencLo + g);
        }
    };

    const int NT = KENC_PAD / 32;   // 158
#pragma unroll
    for (int p = 0; p < ENC_STAGES - 1; p++) {   // stages 0..2
        cp_stage(p, p);
        cp_commit();
    }
#pragma unroll 1
    for (int kt = 0; kt < NT; kt++) {
        const int s = kt & (ENC_STAGES - 1);
        cp_wait<ENC_STAGES - 2>();
        __syncthreads();
        // issue stage kt+3 into buffer (kt+3)%4 == (kt-1)%4 — safe: all warps
        // passed the barrier, so tile kt-1's MMAs are complete block-wide.
        if (kt + ENC_STAGES - 1 < NT) cp_stage(kt + ENC_STAGES - 1, (kt + ENC_STAGES - 1) & (ENC_STAGES - 1));
        cp_commit();   // empty group when past the end keeps wait_group semantics aligned

        const uint32_t base = sbase + (uint32_t)s * 51200u;
#pragma unroll
        for (int ks = 0; ks < 2; ks++) {
            const int kk = ks * 16;
            uint32_t ahi[2][4], alo[2][4];
#pragma unroll
            for (int mt = 0; mt < 2; mt++) {
                uint32_t o = (uint32_t)((wm + mt * 16 + (lane & 15)) * 40 +
                                        kk + (lane >> 4) * 8) * 2u;
                ldsm4(ahi[mt], base + o);
                ldsm4(alo[mt], base + 10240u + o);
            }
            uint32_t bhi[3][4], blo[3][4];
#pragma unroll
            for (int pr = 0; pr < 3; pr++) {
                int n = wn + pr * 16 + (lane & 7) + ((lane >> 4) & 1) * 8;
                uint32_t o = (uint32_t)(n * 40 + kk + ((lane >> 3) & 1) * 8) * 2u;
                ldsm4(bhi[pr], base + 20480u + o);
                ldsm4(blo[pr], base + 35840u + o);
            }
#pragma unroll
            for (int mt = 0; mt < 2; mt++)
#pragma unroll
                for (int nt = 0; nt < 6; nt++) {
                    const uint32_t* bh = &bhi[nt >> 1][(nt & 1) * 2];
                    const uint32_t* bl = &blo[nt >> 1][(nt & 1) * 2];
                    mma16816(acc[mt][nt], ahi[mt], bh);
                    mma16816(acc[mt][nt], ahi[mt], bl);
                    mma16816(acc[mt][nt], alo[mt], bh);
                }
        }
    }

    // epilogue -> g_H fp32 (+ split for base cols < 64)
#pragma unroll
    for (int mt = 0; mt < 2; mt++) {
        int r = row0 + wm + mt * 16 + (lane >> 2);
#pragma unroll
        for (int nt = 0; nt < 6; nt++) {
            int cg = wn + nt * 8 + (lane & 3) * 2;
#pragma unroll
            for (int half = 0; half < 2; half++) {
                int rr = r + half * 8;
                float v0 = acc[mt][nt][half * 2], v1 = acc[mt][nt][half * 2 + 1];
                *(float2*)(g_H + (size_t)rr * NJ + cg) = make_float2(v0, v1);
                if (cg < 64) {
                    uint32_t h, l;
                    split2(v0, v1, h, l);
                    *(uint32_t*)(g_Hhi + (size_t)rr * NJ + cg) = h;
                    *(uint32_t*)(g_Hlo + (size_t)rr * NJ + cg) = l;
                }
            }
        }
    }
}

// ---------------- heads: one CTA per context pair ----------------------------
__global__ __launch_bounds__(256) void heads_kernel() {
    __shared__ float Ms[4096];
    const int pair = blockIdx.x;
    const int tid = threadIdx.x, wid = tid >> 5, lane = tid & 31;
    const float* M = (pair < CARD_B * CARD_B)
                         ? g_MbT + (size_t)pair * 4096
                         : g_McT + (size_t)(pair - CARD_B * CARD_B) * 4096;
    const int colbase = (pair < CARD_B * CARD_B) ? 64 : 128;
    for (int i = tid; i < 4096; i += 256) Ms[i] = M[i];
    __syncthreads();
    const int off = g_off[pair], cnt = g_off[pair + 1] - off;
    for (int i = wid; i < cnt; i += 8) {
        int row = g_rows[off + i];
        float2 x = *(const float2*)(g_H + (size_t)row * NJ + colbase + lane * 2);
        float y0 = 0.f, y1 = 0.f;
#pragma unroll
        for (int li = 0; li < 32; li++) {
            float vx = __shfl_sync(0xffffffffu, x.x, li);
            float vy = __shfl_sync(0xffffffffu, x.y, li);
            int l0 = li * 2;
            y0 = fmaf(vx, Ms[l0 * 64 + lane], y0);
            y1 = fmaf(vx, Ms[l0 * 64 + 32 + lane], y1);
            y0 = fmaf(vy, Ms[(l0 + 1) * 64 + lane], y0);
            y1 = fmaf(vy, Ms[(l0 + 1) * 64 + 32 + lane], y1);
        }
        size_t o = (size_t)row * NJ + colbase;
        store_split(o + lane, y0);
        store_split(o + 32 + lane, y1);
    }
}

// ---------------- decode: out = Hsplit @ WdT^T --------------------------------
// 512 threads, 16 warps 4Mx4N (warp 32x32). Tile 128x128, BK=32, 6 k-tiles,
// double-buffered pure cp.async.
// Stage bytes: Ahi@0 | Alo@10240 | Bhi@20480 | Blo@30720 ; 40960/stage.
#define DEC_SMEM_BYTES (2 * 40960)
__global__ __launch_bounds__(512, 1) void decode_kernel(float* __restrict__ out) {
    extern __shared__ __nv_bfloat16 sm[];
    const uint32_t sbase = s2u(sm);
    const int tid = threadIdx.x, wid = tid >> 5, lane = tid & 31;
    const int row0 = blockIdx.y * 128;
    const int col0 = blockIdx.x * 128;
    const int wm = (wid & 3) * 32, wn = (wid >> 2) * 32;

    const int r_c = tid >> 2, c_c = tid & 3;
    auto cp_stage = [&](int kt, int s) {
        const int k0 = kt * 32;
        uint32_t base = sbase + (uint32_t)s * 40960u;
        uint32_t o = (uint32_t)(r_c * 40 + c_c * 8) * 2u;
        size_t ga = (size_t)(row0 + r_c) * NJ + k0 + c_c * 8;
        size_t gb = (size_t)(col0 + r_c) * NJ + k0 + c_c * 8;
        cp16(base + o,           g_Hhi + ga);
        cp16(base + 10240u + o,  g_Hlo + ga);
        cp16(base + 20480u + o,  g_WdTHi + gb);
        cp16(base + 30720u + o,  g_WdTLo + gb);
    };

    float acc[2][4][4];
#pragma unroll
    for (int i = 0; i < 2; i++)
#pragma unroll
        for (int j = 0; j < 4; j++)
#pragma unroll
            for (int k = 0; k < 4; k++) acc[i][j][k] = 0.f;

    cp_stage(0, 0);
    cp_commit();
#pragma unroll 1
    for (int kt = 0; kt < 6; kt++) {
        const int s = kt & 1;
        cp_wait<0>();
        __syncthreads();
        if (kt + 1 < 6) {
            cp_stage(kt + 1, s ^ 1);
            cp_commit();
        }
        const uint32_t base = sbase + (uint32_t)s * 40960u;
#pragma unroll
        for (int ks = 0; ks < 2; ks++) {
            const int kk = ks * 16;
            uint32_t ahi[2][4], alo[2][4];
#pragma unroll
            for (int mt = 0; mt < 2; mt++) {
                uint32_t o = (uint32_t)((wm + mt * 16 + (lane & 15)) * 40 +
                                        kk + (lane >> 4) * 8) * 2u;
                ldsm4(ahi[mt], base + o);
                ldsm4(alo[mt], base + 10240u + o);
            }
            uint32_t bhi[2][4], blo[2][4];
#pragma unroll
            for (int pr = 0; pr < 2; pr++) {
                int n = wn + pr * 16 + (lane & 7) + ((lane >> 4) & 1) * 8;
                uint32_t o = (uint32_t)(n * 40 + kk + ((lane >> 3) & 1) * 8) * 2u;
                ldsm4(bhi[pr], base + 20480u + o);
                ldsm4(blo[pr], base + 30720u + o);
            }
#pragma unroll
            for (int mt = 0; mt < 2; mt++)
#pragma unroll
                for (int nt = 0; nt < 4; nt++) {
                    const uint32_t* bh = &bhi[nt >> 1][(nt & 1) * 2];
                    const uint32_t* bl = &blo[nt >> 1][(nt & 1) * 2];
                    mma16816(acc[mt][nt], ahi[mt], bh);
                    mma16816(acc[mt][nt], ahi[mt], bl);
                    mma16816(acc[mt][nt], alo[mt], bh);
                }
        }
    }

#pragma unroll
    for (int mt = 0; mt < 2; mt++) {
        int r = row0 + wm + mt * 16 + (lane >> 2);
#pragma unroll
        for (int nt = 0; nt < 4; nt++) {
            int cg = col0 + wn + nt * 8 + (lane & 3) * 2;
            if (cg < ND) {
                *(float2*)(out + (size_t)r * ND + cg) =
                    make_float2(acc[mt][nt][0], acc[mt][nt][1]);
                *(float2*)(out + (size_t)(r + 8) * ND + cg) =
                    make_float2(acc[mt][nt][2], acc[mt][nt][3]);
            }
        }
    }
}

// ---------------- launch --------------------------------------------------------
extern "C" void kernel_launch(void* const* d_in, const int* in_sizes, int n_in,
                              void* d_out, int out_size) {
    const float* expr = (const float*)d_in[0];
    const int* sb = (const int*)d_in[1];
    const int* tb = (const int*)d_in[2];
    const int* sc = (const int*)d_in[3];
    const int* tc = (const int*)d_in[4];
    const float* Wb  = (const float*)d_in[5];
    const float* Web = (const float*)d_in[6];
    const float* Wdb = (const float*)d_in[7];
    const float* Whb = (const float*)d_in[8];
    const float* Wec = (const float*)d_in[9];
    const float* Wdc = (const float*)d_in[10];
    const float* Whc = (const float*)d_in[11];
    float* out = (float*)d_out;

    cudaFuncSetAttribute(encode_kernel, cudaFuncAttributeMaxDynamicSharedMemorySize,
                         ENC_SMEM_BYTES);
    cudaFuncSetAttribute(decode_kernel, cudaFuncAttributeMaxDynamicSharedMemorySize,
                         DEC_SMEM_BYTES);

    // Order chosen so the 4th launch (the one ncu captures) is encode_kernel.
    pack_enc_kernel<<<(NJ * KENC_PAD) / 256, 256>>>(Wb, Web, Wec);
    split_expr_kernel<<<(int)(((size_t)NB * KENC_PAD) / (256 * 8)), 256>>>(expr);
    composite_kernel<<<NBIN, 256>>>(Whb, Whc);
    encode_kernel<<<NB / 128, 512, ENC_SMEM_BYTES>>>();
    bucket_all_kernel<<<1, 1024>>>(sb, tb, sc, tc);
    heads_kernel<<<NBIN, 256>>>();
    pack_dec_kernel<<<(NDEC_PAD * NJ) / 256, 256>>>(Wb, Wdb, Wdc);
    decode_kernel<<<dim3(NDEC_PAD / 128, NB / 128), 512, DEC_SMEM_BYTES>>>(out);
}

// round 8
// speedup vs baseline: 1.1107x; 1.1107x over previous
#include <cuda_runtime.h>
#include <cuda_bf16.h>
#include <cstdint>

#define NB 16384
#define ND 5000
#define NJ 192
#define KENC_PAD 5056          // 158 * 32
#define NDEC_PAD 5120          // 40 * 128
#define DEC_SCALE 0.0159f
#define CARD_B 24
#define CARD_C 10
#define NBIN (CARD_B * CARD_B + CARD_C * CARD_C)   // 676

// ---------------- device-global scratch --------------------------------------
__device__ __align__(16) float         g_H[NB * NJ];
__device__ __align__(16) __nv_bfloat16 g_Hhi[NB * NJ];
__device__ __align__(16) __nv_bfloat16 g_Hlo[NB * NJ];
__device__ __align__(16) __nv_bfloat16 g_WencHi[NJ * KENC_PAD];
__device__ __align__(16) __nv_bfloat16 g_WencLo[NJ * KENC_PAD];
__device__ __align__(16) __nv_bfloat16 g_WdTHi[NDEC_PAD * NJ];
__device__ __align__(16) float         g_MbT[CARD_B * CARD_B * 4096];
__device__ __align__(16) __nv_bfloat16 g_WdTLo[NDEC_PAD * NJ];
__device__ __align__(16) float         g_McT[CARD_C * CARD_C * 4096];
__device__ int g_off[NBIN + 1];
__device__ int g_rows[2 * NB];

// ---------------- PTX helpers -------------------------------------------------
__device__ __forceinline__ uint32_t s2u(const void* p) {
    return (uint32_t)__cvta_generic_to_shared(p);
}
__device__ __forceinline__ void cp16(uint32_t dst, const void* src) {
    asm volatile("cp.async.cg.shared.global [%0], [%1], 16;" :: "r"(dst), "l"(src));
}
__device__ __forceinline__ void cp_commit() {
    asm volatile("cp.async.commit_group;" ::: "memory");
}
template <int N> __device__ __forceinline__ void cp_wait() {
    asm volatile("cp.async.wait_group %0;" :: "n"(N) : "memory");
}
__device__ __forceinline__ void sts128(uint32_t a, uint32_t x, uint32_t y,
                                       uint32_t z, uint32_t w) {
    asm volatile("st.shared.v4.b32 [%0], {%1,%2,%3,%4};"
                 :: "r"(a), "r"(x), "r"(y), "r"(z), "r"(w) : "memory");
}
__device__ __forceinline__ void ldsm4(uint32_t* r, uint32_t a) {
    asm volatile("ldmatrix.sync.aligned.m8n8.x4.shared.b16 {%0,%1,%2,%3}, [%4];"
                 : "=r"(r[0]), "=r"(r[1]), "=r"(r[2]), "=r"(r[3]) : "r"(a));
}
__device__ __forceinline__ void mma16816(float* c, const uint32_t* a, const uint32_t* b) {
    asm volatile("mma.sync.aligned.m16n8k16.row.col.f32.bf16.bf16.f32 "
                 "{%0,%1,%2,%3},{%4,%5,%6,%7},{%8,%9},{%0,%1,%2,%3};"
                 : "+f"(c[0]), "+f"(c[1]), "+f"(c[2]), "+f"(c[3])
                 : "r"(a[0]), "r"(a[1]), "r"(a[2]), "r"(a[3]), "r"(b[0]), "r"(b[1]));
}
__device__ __forceinline__ void split2(float f0, float f1, uint32_t& h, uint32_t& l) {
    __nv_bfloat16 h0 = __float2bfloat16_rn(f0);
    __nv_bfloat16 h1 = __float2bfloat16_rn(f1);
    __nv_bfloat16 l0 = __float2bfloat16_rn(f0 - __bfloat162float(h0));
    __nv_bfloat16 l1 = __float2bfloat16_rn(f1 - __bfloat162float(h1));
    h = (uint32_t)__bfloat16_as_ushort(h0) | ((uint32_t)__bfloat16_as_ushort(h1) << 16);
    l = (uint32_t)__bfloat16_as_ushort(l0) | ((uint32_t)__bfloat16_as_ushort(l1) << 16);
}
__device__ __forceinline__ void store_split(size_t i, float v) {
    __nv_bfloat16 h = __float2bfloat16_rn(v);
    g_Hhi[i] = h;
    g_Hlo[i] = __float2bfloat16_rn(v - __bfloat162float(h));
}

// ---------------- pack kernels ------------------------------------------------
__global__ void pack_enc_kernel(const float* __restrict__ Wb,
                                const float* __restrict__ Web,
                                const float* __restrict__ Wec) {
    int idx = blockIdx.x * blockDim.x + threadIdx.x;
    int j = idx / KENC_PAD, d = idx - j * KENC_PAD;
    float v = 0.f;
    if (d < ND) {
        if (j < 64)       v = Wb[j * ND + d];
        else if (j < 128) v = Web[(j - 64) * ND + d];
        else              v = Wec[(j - 128) * ND + d];
    }
    __nv_bfloat16 h = __float2bfloat16_rn(v);
    g_WencHi[idx] = h;
    g_WencLo[idx] = __float2bfloat16_rn(v - __bfloat162float(h));
}
__global__ void pack_dec_kernel(const float* __restrict__ Wb,
                                const float* __restrict__ Wdb,
                                const float* __restrict__ Wdc) {
    int idx = blockIdx.x * blockDim.x + threadIdx.x;
    int n = idx / NJ, j = idx - n * NJ;
    float v = 0.f;
    if (n < ND) {
        if (j < 64)       v = Wb[j * ND + n];
        else if (j < 128) v = Wdb[n * 64 + (j - 64)];
        else              v = Wdc[n * 64 + (j - 128)];
    }
    __nv_bfloat16 h = __float2bfloat16_rn(v);
    g_WdTHi[idx] = h;
    g_WdTLo[idx] = __float2bfloat16_rn(v - __bfloat162float(h));
}

// ---------------- composite: MT[pair][l][m] = scale * (W[t] @ W[s])[m,l] -----
__global__ __launch_bounds__(256) void composite_kernel(const float* __restrict__ Whb,
                                                        const float* __restrict__ Whc) {
    __shared__ float sT[4096], sS[4096];
    int pair = blockIdx.x;
    const float *Wt, *Ws;
    float* out;
    if (pair < CARD_B * CARD_B) {
        Wt = Whb + (size_t)(pair / CARD_B) * 4096;
        Ws = Whb + (size_t)(pair % CARD_B) * 4096;
        out = g_MbT + (size_t)pair * 4096;
    } else {
        int p = pair - CARD_B * CARD_B;
        Wt = Whc + (size_t)(p / CARD_C) * 4096;
        Ws = Whc + (size_t)(p % CARD_C) * 4096;
        out = g_McT + (size_t)p * 4096;
    }
    int tid = threadIdx.x;
    for (int i = tid; i < 4096; i += 256) { sT[i] = Wt[i]; sS[i] = Ws[i]; }
    __syncthreads();
    int m = tid >> 2, n0 = (tid & 3) * 16;
    float c[16];
#pragma unroll
    for (int j = 0; j < 16; j++) c[j] = 0.f;
    for (int l = 0; l < 64; l++) {
        float a = sT[m * 64 + l];
#pragma unroll
        for (int j = 0; j < 16; j++) c[j] = fmaf(a, sS[l * 64 + n0 + j], c[j]);
    }
#pragma unroll
    for (int j = 0; j < 16; j++) out[(n0 + j) * 64 + m] = c[j] * DEC_SCALE;
}

// ---------------- bucketing: single-CTA fused count/scan/scatter --------------
__global__ __launch_bounds__(1024) void bucket_all_kernel(const int* __restrict__ sb,
                                                          const int* __restrict__ tb,
                                                          const int* __restrict__ sc,
                                                          const int* __restrict__ tc) {
    __shared__ int scnt[NBIN];
    __shared__ int scur[NBIN];
    const int tid = threadIdx.x;
    for (int i = tid; i < NBIN; i += 1024) scnt[i] = 0;
    __syncthreads();
    for (int row = tid; row < NB; row += 1024) {
        atomicAdd(&scnt[tb[row] * CARD_B + sb[row]], 1);
        atomicAdd(&scnt[CARD_B * CARD_B + tc[row] * CARD_C + sc[row]], 1);
    }
    __syncthreads();
    if (tid == 0) {
        int acc = 0;
        for (int i = 0; i < NBIN; i++) {
            scur[i] = acc;
            g_off[i] = acc;
            acc += scnt[i];
        }
        g_off[NBIN] = acc;
    }
    __syncthreads();
    for (int row = tid; row < NB; row += 1024) {
        int pb = tb[row] * CARD_B + sb[row];
        int pc = CARD_B * CARD_B + tc[row] * CARD_C + sc[row];
        g_rows[atomicAdd(&scur[pb], 1)] = row;
        g_rows[atomicAdd(&scur[pc], 1)] = row;
    }
}

// ---------------- encode (R6 config: in-kernel split, measured best net) ------
// 512 threads, 16 warps 4Mx4N (warp 32x48). Tile 128x192, BK=32, double-buffered.
// Stage bytes: Ahi@0 (10240) | Alo@10240 | Bhi@20480 (15360) | Blo@35840 ; 51200/stage.
#define ENC_SMEM_BYTES (2 * 51200)
__global__ __launch_bounds__(512, 1) void encode_kernel(const float* __restrict__ A) {
    extern __shared__ __nv_bfloat16 sm[];
    const uint32_t sbase = s2u(sm);
    const int tid = threadIdx.x, wid = tid >> 5, lane = tid & 31;
    const int row0 = blockIdx.x * 128;
    const int wm = (wid & 3) * 32, wn = (wid >> 2) * 48;

    float acc[2][6][4];
#pragma unroll
    for (int i = 0; i < 2; i++)
#pragma unroll
        for (int j = 0; j < 6; j++)
#pragma unroll
            for (int k = 0; k < 4; k++) acc[i][j][k] = 0.f;

    float4 av0, av1;
    const int r_a = tid >> 2, c_a = tid & 3;
    auto ldgA = [&](int kt) {
        const int kg = kt * 32 + c_a * 8;
        if (kg < ND) {
            const float4* p = (const float4*)(A + (size_t)(row0 + r_a) * ND + kg);
            av0 = p[0]; av1 = p[1];
        } else {
            av0 = make_float4(0.f, 0.f, 0.f, 0.f);
            av1 = av0;
        }
    };
    auto stsA = [&](int s) {
        uint32_t base = sbase + (uint32_t)s * 51200u;
        uint32_t h[4], l[4];
        split2(av0.x, av0.y, h[0], l[0]);
        split2(av0.z, av0.w, h[1], l[1]);
        split2(av1.x, av1.y, h[2], l[2]);
        split2(av1.z, av1.w, h[3], l[3]);
        uint32_t o = (uint32_t)(r_a * 40 + c_a * 8) * 2u;
        sts128(base + o,          h[0], h[1], h[2], h[3]);
        sts128(base + 10240u + o, l[0], l[1], l[2], l[3]);
    };
    auto cpB = [&](int kt, int s) {
        const int k0 = kt * 32;
        uint32_t base = sbase + (uint32_t)s * 51200u;
        {
            int n = tid >> 2, c = tid & 3;
            uint32_t o = (uint32_t)(n * 40 + c * 8) * 2u;
            cp16(base + 20480u + o, g_WencHi + (size_t)n * KENC_PAD + k0 + c * 8);
            cp16(base + 35840u + o, g_WencLo + (size_t)n * KENC_PAD + k0 + c * 8);
        }
        if (tid < 256) {
            int idx = tid + 512;
            int n = idx >> 2, c = idx & 3;
            uint32_t o = (uint32_t)(n * 40 + c * 8) * 2u;
            cp16(base + 20480u + o, g_WencHi + (size_t)n * KENC_PAD + k0 + c * 8);
            cp16(base + 35840u + o, g_WencLo + (size_t)n * KENC_PAD + k0 + c * 8);
        }
    };

    const int NT = KENC_PAD / 32;   // 158
    ldgA(0);
    cpB(0, 0);
    cp_commit();
#pragma unroll 1
    for (int kt = 0; kt < NT; kt++) {
        const int s = kt & 1;
        stsA(s);
        cp_wait<0>();
        __syncthreads();
        if (kt + 1 < NT) {
            ldgA(kt + 1);
            cpB(kt + 1, s ^ 1);
            cp_commit();
        }
        const uint32_t base = sbase + (uint32_t)s * 51200u;
#pragma unroll
        for (int ks = 0; ks < 2; ks++) {
            const int kk = ks * 16;
            uint32_t ahi[2][4], alo[2][4];
#pragma unroll
            for (int mt = 0; mt < 2; mt++) {
                uint32_t o = (uint32_t)((wm + mt * 16 + (lane & 15)) * 40 +
                                        kk + (lane >> 4) * 8) * 2u;
                ldsm4(ahi[mt], base + o);
                ldsm4(alo[mt], base + 10240u + o);
            }
            uint32_t bhi[3][4], blo[3][4];
#pragma unroll
            for (int pr = 0; pr < 3; pr++) {
                int n = wn + pr * 16 + (lane & 7) + ((lane >> 4) & 1) * 8;
                uint32_t o = (uint32_t)(n * 40 + kk + ((lane >> 3) & 1) * 8) * 2u;
                ldsm4(bhi[pr], base + 20480u + o);
                ldsm4(blo[pr], base + 35840u + o);
            }
#pragma unroll
            for (int mt = 0; mt < 2; mt++)
#pragma unroll
                for (int nt = 0; nt < 6; nt++) {
                    const uint32_t* bh = &bhi[nt >> 1][(nt & 1) * 2];
                    const uint32_t* bl = &blo[nt >> 1][(nt & 1) * 2];
                    mma16816(acc[mt][nt], ahi[mt], bh);
                    mma16816(acc[mt][nt], ahi[mt], bl);
                    mma16816(acc[mt][nt], alo[mt], bh);
                }
        }
    }

#pragma unroll
    for (int mt = 0; mt < 2; mt++) {
        int r = row0 + wm + mt * 16 + (lane >> 2);
#pragma unroll
        for (int nt = 0; nt < 6; nt++) {
            int cg = wn + nt * 8 + (lane & 3) * 2;
#pragma unroll
            for (int half = 0; half < 2; half++) {
                int rr = r + half * 8;
                float v0 = acc[mt][nt][half * 2], v1 = acc[mt][nt][half * 2 + 1];
                *(float2*)(g_H + (size_t)rr * NJ + cg) = make_float2(v0, v1);
                if (cg < 64) {
                    uint32_t h, l;
                    split2(v0, v1, h, l);
                    *(uint32_t*)(g_Hhi + (size_t)rr * NJ + cg) = h;
                    *(uint32_t*)(g_Hlo + (size_t)rr * NJ + cg) = l;
                }
            }
        }
    }
}

// ---------------- heads: one CTA per context pair ----------------------------
__global__ __launch_bounds__(256) void heads_kernel() {
    __shared__ float Ms[4096];
    const int pair = blockIdx.x;
    const int tid = threadIdx.x, wid = tid >> 5, lane = tid & 31;
    const float* M = (pair < CARD_B * CARD_B)
                         ? g_MbT + (size_t)pair * 4096
                         : g_McT + (size_t)(pair - CARD_B * CARD_B) * 4096;
    const int colbase = (pair < CARD_B * CARD_B) ? 64 : 128;
    for (int i = tid; i < 4096; i += 256) Ms[i] = M[i];
    __syncthreads();
    const int off = g_off[pair], cnt = g_off[pair + 1] - off;
    for (int i = wid; i < cnt; i += 8) {
        int row = g_rows[off + i];
        float2 x = *(const float2*)(g_H + (size_t)row * NJ + colbase + lane * 2);
        float y0 = 0.f, y1 = 0.f;
#pragma unroll
        for (int li = 0; li < 32; li++) {
            float vx = __shfl_sync(0xffffffffu, x.x, li);
            float vy = __shfl_sync(0xffffffffu, x.y, li);
            int l0 = li * 2;
            y0 = fmaf(vx, Ms[l0 * 64 + lane], y0);
            y1 = fmaf(vx, Ms[l0 * 64 + 32 + lane], y1);
            y0 = fmaf(vy, Ms[(l0 + 1) * 64 + lane], y0);
            y1 = fmaf(vy, Ms[(l0 + 1) * 64 + 32 + lane], y1);
        }
        size_t o = (size_t)row * NJ + colbase;
        store_split(o + lane, y0);
        store_split(o + 32 + lane, y1);
    }
}

// ---------------- decode: PERSISTENT col-panel kernel -------------------------
// grid (40, 3). Each CTA owns a 128-col B panel (hi+lo resident in smem) and
// streams 64-row A tiles (double-buffered cp.async) over its share of 256
// row-tiles. 256 threads, 8 warps 2Mx4N (warp 32x32).
// smem bytes (row stride 200 halves = 400B):
//   Bhi@0 (51200) | Blo@51200 | A stage s @ 102400+s*51200: Ahi(25600)+Alo(25600)
#define DEC_SMEM_BYTES 204800
__global__ __launch_bounds__(256, 1) void decode_kernel(float* __restrict__ out) {
    extern __shared__ __nv_bfloat16 sm[];
    const uint32_t sbase = s2u(sm);
    const int tid = threadIdx.x, wid = tid >> 5, lane = tid & 31;
    const int col0 = blockIdx.x * 128;
    const int rowg = blockIdx.y;                     // 0..2
    const int start = rowg * 85 + (rowg > 0 ? 1 : 0);
    const int count = (rowg == 0) ? 86 : 85;         // 86+85+85 = 256 row-tiles
    const int wm = (wid & 1) * 32, wn = (wid >> 1) * 32;

    // B panel load (once)
    for (int i = tid; i < 3072; i += 256) {          // 128 rows x 24 chunks
        int n = i / 24, c = i - n * 24;
        uint32_t o = (uint32_t)(n * 200 + c * 8) * 2u;
        size_t g = (size_t)(col0 + n) * NJ + c * 8;
        cp16(sbase + o,          g_WdTHi + g);
        cp16(sbase + 51200u + o, g_WdTLo + g);
    }

    // Per-thread fixed A-chunk map: 6 chunks/thread (64 rows x 24 chunks / 256)
    uint32_t a_off[6];
    int a_rel[6];
#pragma unroll
    for (int u = 0; u < 6; u++) {
        int i = tid + u * 256;
        int r = i / 24, c = i - r * 24;
        a_off[u] = (uint32_t)(r * 200 + c * 8) * 2u;
        a_rel[u] = r * NJ + c * 8;
    }
    auto cpA = [&](int tile, int s) {                // tile = global 64-row tile idx
        uint32_t base = sbase + 102400u + (uint32_t)s * 51200u;
        size_t g0 = (size_t)tile * 64 * NJ;
#pragma unroll
        for (int u = 0; u < 6; u++) {
            cp16(base + a_off[u],           g_Hhi + g0 + a_rel[u]);
            cp16(base + 25600u + a_off[u],  g_Hlo + g0 + a_rel[u]);
        }
    };

    cpA(start, 0);
    cp_commit();

    float acc[2][4][4];
#pragma unroll 1
    for (int t = 0; t < count; t++) {
        const int s = t & 1;
        cp_wait<0>();
        __syncthreads();
        if (t + 1 < count) cpA(start + t + 1, s ^ 1);
        cp_commit();

#pragma unroll
        for (int i = 0; i < 2; i++)
#pragma unroll
            for (int j = 0; j < 4; j++)
#pragma unroll
                for (int k = 0; k < 4; k++) acc[i][j][k] = 0.f;

        const uint32_t abase = sbase + 102400u + (uint32_t)s * 51200u;
#pragma unroll
        for (int ks = 0; ks < 12; ks++) {
            const int kk = ks * 16;
            uint32_t ahi[2][4], alo[2][4];
#pragma unroll
            for (int mt = 0; mt < 2; mt++) {
                uint32_t o = (uint32_t)((wm + mt * 16 + (lane & 15)) * 200 +
                                        kk + (lane >> 4) * 8) * 2u;
                ldsm4(ahi[mt], abase + o);
                ldsm4(alo[mt], abase + 25600u + o);
            }
            uint32_t bhi[2][4], blo[2][4];
#pragma unroll
            for (int pr = 0; pr < 2; pr++) {
                int n = wn + pr * 16 + (lane & 7) + ((lane >> 4) & 1) * 8;
                uint32_t o = (uint32_t)(n * 200 + kk + ((lane >> 3) & 1) * 8) * 2u;
                ldsm4(bhi[pr], sbase + o);
                ldsm4(blo[pr], sbase + 51200u + o);
            }
#pragma unroll
            for (int mt = 0; mt < 2; mt++)
#pragma unroll
                for (int nt = 0; nt < 4; nt++) {
                    const uint32_t* bh = &bhi[nt >> 1][(nt & 1) * 2];
                    const uint32_t* bl = &blo[nt >> 1][(nt & 1) * 2];
                    mma16816(acc[mt][nt], ahi[mt], bh);
                    mma16816(acc[mt][nt], ahi[mt], bl);
                    mma16816(acc[mt][nt], alo[mt], bh);
                }
        }

        const int trow0 = (start + t) * 64;
#pragma unroll
        for (int mt = 0; mt < 2; mt++) {
            int r = trow0 + wm + mt * 16 + (lane >> 2);
#pragma unroll
            for (int nt = 0; nt < 4; nt++) {
                int cg = col0 + wn + nt * 8 + (lane & 3) * 2;
                if (cg < ND) {
                    *(float2*)(out + (size_t)r * ND + cg) =
                        make_float2(acc[mt][nt][0], acc[mt][nt][1]);
                    *(float2*)(out + (size_t)(r + 8) * ND + cg) =
                        make_float2(acc[mt][nt][2], acc[mt][nt][3]);
                }
            }
        }
    }
}

// ---------------- launch --------------------------------------------------------
extern "C" void kernel_launch(void* const* d_in, const int* in_sizes, int n_in,
                              void* d_out, int out_size) {
    const float* expr = (const float*)d_in[0];
    const int* sb = (const int*)d_in[1];
    const int* tb = (const int*)d_in[2];
    const int* sc = (const int*)d_in[3];
    const int* tc = (const int*)d_in[4];
    const float* Wb  = (const float*)d_in[5];
    const float* Web = (const float*)d_in[6];
    const float* Wdb = (const float*)d_in[7];
    const float* Whb = (const float*)d_in[8];
    const float* Wec = (const float*)d_in[9];
    const float* Wdc = (const float*)d_in[10];
    const float* Whc = (const float*)d_in[11];
    float* out = (float*)d_out;

    cudaFuncSetAttribute(encode_kernel, cudaFuncAttributeMaxDynamicSharedMemorySize,
                         ENC_SMEM_BYTES);
    cudaFuncSetAttribute(decode_kernel, cudaFuncAttributeMaxDynamicSharedMemorySize,
                         DEC_SMEM_BYTES);

    // Order keeps encode as the 4th launch (the one ncu captures).
    pack_enc_kernel<<<(NJ * KENC_PAD) / 256, 256>>>(Wb, Web, Wec);
    composite_kernel<<<NBIN, 256>>>(Whb, Whc);
    bucket_all_kernel<<<1, 1024>>>(sb, tb, sc, tc);
    encode_kernel<<<NB / 128, 512, ENC_SMEM_BYTES>>>(expr);
    heads_kernel<<<NBIN, 256>>>();
    pack_dec_kernel<<<(NDEC_PAD * NJ) / 256, 256>>>(Wb, Wdb, Wdc);
    decode_kernel<<<dim3(40, 3), 256, DEC_SMEM_BYTES>>>(out);
}

// round 9
// speedup vs baseline: 1.4380x; 1.2947x over previous
#include <cuda_runtime.h>
#include <cuda_fp16.h>
#include <cstdint>

#define NB 16384
#define ND 5000
#define NJ 192
#define KENC_PAD 5056          // 158 * 32
#define NDEC_PAD 5120          // 40 * 128
#define DEC_SCALE 0.0159f
#define CARD_B 24
#define CARD_C 10
#define NBIN (CARD_B * CARD_B + CARD_C * CARD_C)   // 676

// ---------------- device-global scratch --------------------------------------
__device__ __align__(16) float  g_H[NB * NJ];
__device__ __align__(16) __half g_Hhi[NB * NJ];
__device__ __align__(16) __half g_Hlo[NB * NJ];
__device__ __align__(16) __half g_WencH[NJ * KENC_PAD];     // fp16 weights (single)
__device__ __align__(16) __half g_WdTH[NDEC_PAD * NJ];      // fp16 weights (single)
__device__ __align__(16) float  g_MbT[CARD_B * CARD_B * 4096];
__device__ __align__(16) float  g_McT[CARD_C * CARD_C * 4096];
__device__ int g_off[NBIN + 1];
__device__ int g_rows[2 * NB];

// ---------------- PTX helpers -------------------------------------------------
__device__ __forceinline__ uint32_t s2u(const void* p) {
    return (uint32_t)__cvta_generic_to_shared(p);
}
__device__ __forceinline__ void cp16(uint32_t dst, const void* src) {
    asm volatile("cp.async.cg.shared.global [%0], [%1], 16;" :: "r"(dst), "l"(src));
}
__device__ __forceinline__ void cp_commit() {
    asm volatile("cp.async.commit_group;" ::: "memory");
}
template <int N> __device__ __forceinline__ void cp_wait() {
    asm volatile("cp.async.wait_group %0;" :: "n"(N) : "memory");
}
__device__ __forceinline__ void sts128(uint32_t a, uint32_t x, uint32_t y,
                                       uint32_t z, uint32_t w) {
    asm volatile("st.shared.v4.b32 [%0], {%1,%2,%3,%4};"
                 :: "r"(a), "r"(x), "r"(y), "r"(z), "r"(w) : "memory");
}
__device__ __forceinline__ void ldsm4(uint32_t* r, uint32_t a) {
    asm volatile("ldmatrix.sync.aligned.m8n8.x4.shared.b16 {%0,%1,%2,%3}, [%4];"
                 : "=r"(r[0]), "=r"(r[1]), "=r"(r[2]), "=r"(r[3]) : "r"(a));
}
__device__ __forceinline__ void mma16816(float* c, const uint32_t* a, const uint32_t* b) {
    asm volatile("mma.sync.aligned.m16n8k16.row.col.f32.f16.f16.f32 "
                 "{%0,%1,%2,%3},{%4,%5,%6,%7},{%8,%9},{%0,%1,%2,%3};"
                 : "+f"(c[0]), "+f"(c[1]), "+f"(c[2]), "+f"(c[3])
                 : "r"(a[0]), "r"(a[1]), "r"(a[2]), "r"(a[3]), "r"(b[0]), "r"(b[1]));
}
__device__ __forceinline__ uint16_t h_as_u(__half h) { return __half_as_ushort(h); }
__device__ __forceinline__ void split2h(float f0, float f1, uint32_t& h, uint32_t& l) {
    __half h0 = __float2half_rn(f0);
    __half h1 = __float2half_rn(f1);
    __half l0 = __float2half_rn(f0 - __half2float(h0));
    __half l1 = __float2half_rn(f1 - __half2float(h1));
    h = (uint32_t)h_as_u(h0) | ((uint32_t)h_as_u(h1) << 16);
    l = (uint32_t)h_as_u(l0) | ((uint32_t)h_as_u(l1) << 16);
}
__device__ __forceinline__ void store_split(size_t i, float v) {
    __half h = __float2half_rn(v);
    g_Hhi[i] = h;
    g_Hlo[i] = __float2half_rn(v - __half2float(h));
}

// ---------------- pack kernels ------------------------------------------------
__global__ void pack_enc_kernel(const float* __restrict__ Wb,
                                const float* __restrict__ Web,
                                const float* __restrict__ Wec) {
    int idx = blockIdx.x * blockDim.x + threadIdx.x;
    int j = idx / KENC_PAD, d = idx - j * KENC_PAD;
    float v = 0.f;
    if (d < ND) {
        if (j < 64)       v = Wb[j * ND + d];
        else if (j < 128) v = Web[(j - 64) * ND + d];
        else              v = Wec[(j - 128) * ND + d];
    }
    g_WencH[idx] = __float2half_rn(v);
}
__global__ void pack_dec_kernel(const float* __restrict__ Wb,
                                const float* __restrict__ Wdb,
                                const float* __restrict__ Wdc) {
    int idx = blockIdx.x * blockDim.x + threadIdx.x;
    int n = idx / NJ, j = idx - n * NJ;
    float v = 0.f;
    if (n < ND) {
        if (j < 64)       v = Wb[j * ND + n];
        else if (j < 128) v = Wdb[n * 64 + (j - 64)];
        else              v = Wdc[n * 64 + (j - 128)];
    }
    g_WdTH[idx] = __float2half_rn(v);
}

// ---------------- composite: MT[pair][l][m] = scale * (W[t] @ W[s])[m,l] -----
__global__ __launch_bounds__(256) void composite_kernel(const float* __restrict__ Whb,
                                                        const float* __restrict__ Whc) {
    __shared__ float sT[4096], sS[4096];
    int pair = blockIdx.x;
    const float *Wt, *Ws;
    float* out;
    if (pair < CARD_B * CARD_B) {
        Wt = Whb + (size_t)(pair / CARD_B) * 4096;
        Ws = Whb + (size_t)(pair % CARD_B) * 4096;
        out = g_MbT + (size_t)pair * 4096;
    } else {
        int p = pair - CARD_B * CARD_B;
        Wt = Whc + (size_t)(p / CARD_C) * 4096;
        Ws = Whc + (size_t)(p % CARD_C) * 4096;
        out = g_McT + (size_t)p * 4096;
    }
    int tid = threadIdx.x;
    for (int i = tid; i < 4096; i += 256) { sT[i] = Wt[i]; sS[i] = Ws[i]; }
    __syncthreads();
    int m = tid >> 2, n0 = (tid & 3) * 16;
    float c[16];
#pragma unroll
    for (int j = 0; j < 16; j++) c[j] = 0.f;
    for (int l = 0; l < 64; l++) {
        float a = sT[m * 64 + l];
#pragma unroll
        for (int j = 0; j < 16; j++) c[j] = fmaf(a, sS[l * 64 + n0 + j], c[j]);
    }
#pragma unroll
    for (int j = 0; j < 16; j++) out[(n0 + j) * 64 + m] = c[j] * DEC_SCALE;
}

// ---------------- bucketing: single-CTA fused count/scan/scatter --------------
__global__ __launch_bounds__(1024) void bucket_all_kernel(const int* __restrict__ sb,
                                                          const int* __restrict__ tb,
                                                          const int* __restrict__ sc,
                                                          const int* __restrict__ tc) {
    __shared__ int scnt[NBIN];
    __shared__ int scur[NBIN];
    const int tid = threadIdx.x;
    for (int i = tid; i < NBIN; i += 1024) scnt[i] = 0;
    __syncthreads();
    for (int row = tid; row < NB; row += 1024) {
        atomicAdd(&scnt[tb[row] * CARD_B + sb[row]], 1);
        atomicAdd(&scnt[CARD_B * CARD_B + tc[row] * CARD_C + sc[row]], 1);
    }
    __syncthreads();
    if (tid == 0) {
        int acc = 0;
        for (int i = 0; i < NBIN; i++) {
            scur[i] = acc;
            g_off[i] = acc;
            acc += scnt[i];
        }
        g_off[NBIN] = acc;
    }
    __syncthreads();
    for (int row = tid; row < NB; row += 1024) {
        int pb = tb[row] * CARD_B + sb[row];
        int pc = CARD_B * CARD_B + tc[row] * CARD_C + sc[row];
        g_rows[atomicAdd(&scur[pb], 1)] = row;
        g_rows[atomicAdd(&scur[pc], 1)] = row;
    }
}

// ---------------- encode: 2-pass fp16 (A split, B single) ---------------------
// 512 threads, 16 warps 4Mx4N (warp 32x48). Tile 128x192, BK=32, double-buffered.
// Stage bytes: Ahi@0 (10240) | Alo@10240 | B@20480 (15360) ; 35840/stage.
#define ENC_SMEM_BYTES (2 * 35840)
__global__ __launch_bounds__(512, 1) void encode_kernel(const float* __restrict__ A) {
    extern __shared__ __half sm[];
    const uint32_t sbase = s2u(sm);
    const int tid = threadIdx.x, wid = tid >> 5, lane = tid & 31;
    const int row0 = blockIdx.x * 128;
    const int wm = (wid & 3) * 32, wn = (wid >> 2) * 48;

    float acc[2][6][4];
#pragma unroll
    for (int i = 0; i < 2; i++)
#pragma unroll
        for (int j = 0; j < 6; j++)
#pragma unroll
            for (int k = 0; k < 4; k++) acc[i][j][k] = 0.f;

    float4 av0, av1;
    const int r_a = tid >> 2, c_a = tid & 3;
    auto ldgA = [&](int kt) {
        const int kg = kt * 32 + c_a * 8;
        if (kg < ND) {
            const float4* p = (const float4*)(A + (size_t)(row0 + r_a) * ND + kg);
            av0 = p[0]; av1 = p[1];
        } else {
            av0 = make_float4(0.f, 0.f, 0.f, 0.f);
            av1 = av0;
        }
    };
    auto stsA = [&](int s) {
        uint32_t base = sbase + (uint32_t)s * 35840u;
        uint32_t h[4], l[4];
        split2h(av0.x, av0.y, h[0], l[0]);
        split2h(av0.z, av0.w, h[1], l[1]);
        split2h(av1.x, av1.y, h[2], l[2]);
        split2h(av1.z, av1.w, h[3], l[3]);
        uint32_t o = (uint32_t)(r_a * 40 + c_a * 8) * 2u;
        sts128(base + o,          h[0], h[1], h[2], h[3]);
        sts128(base + 10240u + o, l[0], l[1], l[2], l[3]);
    };
    auto cpB = [&](int kt, int s) {
        const int k0 = kt * 32;
        uint32_t base = sbase + (uint32_t)s * 35840u;
        {
            int n = tid >> 2, c = tid & 3;
            uint32_t o = (uint32_t)(n * 40 + c * 8) * 2u;
            cp16(base + 20480u + o, g_WencH + (size_t)n * KENC_PAD + k0 + c * 8);
        }
        if (tid < 256) {
            int idx = tid + 512;
            int n = idx >> 2, c = idx & 3;
            uint32_t o = (uint32_t)(n * 40 + c * 8) * 2u;
            cp16(base + 20480u + o, g_WencH + (size_t)n * KENC_PAD + k0 + c * 8);
        }
    };

    const int NT = KENC_PAD / 32;   // 158
    ldgA(0);
    cpB(0, 0);
    cp_commit();
#pragma unroll 1
    for (int kt = 0; kt < NT; kt++) {
        const int s = kt & 1;
        stsA(s);
        cp_wait<0>();
        __syncthreads();
        if (kt + 1 < NT) {
            ldgA(kt + 1);
            cpB(kt + 1, s ^ 1);
            cp_commit();
        }
        const uint32_t base = sbase + (uint32_t)s * 35840u;
#pragma unroll
        for (int ks = 0; ks < 2; ks++) {
            const int kk = ks * 16;
            uint32_t ahi[2][4], alo[2][4];
#pragma unroll
            for (int mt = 0; mt < 2; mt++) {
                uint32_t o = (uint32_t)((wm + mt * 16 + (lane & 15)) * 40 +
                                        kk + (lane >> 4) * 8) * 2u;
                ldsm4(ahi[mt], base + o);
                ldsm4(alo[mt], base + 10240u + o);
            }
            uint32_t bhi[3][4];
#pragma unroll
            for (int pr = 0; pr < 3; pr++) {
                int n = wn + pr * 16 + (lane & 7) + ((lane >> 4) & 1) * 8;
                uint32_t o = (uint32_t)(n * 40 + kk + ((lane >> 3) & 1) * 8) * 2u;
                ldsm4(bhi[pr], base + 20480u + o);
            }
#pragma unroll
            for (int mt = 0; mt < 2; mt++)
#pragma unroll
                for (int nt = 0; nt < 6; nt++) {
                    const uint32_t* bh = &bhi[nt >> 1][(nt & 1) * 2];
                    mma16816(acc[mt][nt], ahi[mt], bh);
                    mma16816(acc[mt][nt], alo[mt], bh);
                }
        }
    }

    // epilogue -> g_H fp32 (+ fp16 split for base cols < 64)
#pragma unroll
    for (int mt = 0; mt < 2; mt++) {
        int r = row0 + wm + mt * 16 + (lane >> 2);
#pragma unroll
        for (int nt = 0; nt < 6; nt++) {
            int cg = wn + nt * 8 + (lane & 3) * 2;
#pragma unroll
            for (int half = 0; half < 2; half++) {
                int rr = r + half * 8;
                float v0 = acc[mt][nt][half * 2], v1 = acc[mt][nt][half * 2 + 1];
                *(float2*)(g_H + (size_t)rr * NJ + cg) = make_float2(v0, v1);
                if (cg < 64) {
                    uint32_t h, l;
                    split2h(v0, v1, h, l);
                    *(uint32_t*)(g_Hhi + (size_t)rr * NJ + cg) = h;
                    *(uint32_t*)(g_Hlo + (size_t)rr * NJ + cg) = l;
                }
            }
        }
    }
}

// ---------------- heads: one CTA per context pair ----------------------------
__global__ __launch_bounds__(256) void heads_kernel() {
    __shared__ float Ms[4096];
    const int pair = blockIdx.x;
    const int tid = threadIdx.x, wid = tid >> 5, lane = tid & 31;
    const float* M = (pair < CARD_B * CARD_B)
                         ? g_MbT + (size_t)pair * 4096
                         : g_McT + (size_t)(pair - CARD_B * CARD_B) * 4096;
    const int colbase = (pair < CARD_B * CARD_B) ? 64 : 128;
    for (int i = tid; i < 4096; i += 256) Ms[i] = M[i];
    __syncthreads();
    const int off = g_off[pair], cnt = g_off[pair + 1] - off;
    for (int i = wid; i < cnt; i += 8) {
        int row = g_rows[off + i];
        float2 x = *(const float2*)(g_H + (size_t)row * NJ + colbase + lane * 2);
        float y0 = 0.f, y1 = 0.f;
#pragma unroll
        for (int li = 0; li < 32; li++) {
            float vx = __shfl_sync(0xffffffffu, x.x, li);
            float vy = __shfl_sync(0xffffffffu, x.y, li);
            int l0 = li * 2;
            y0 = fmaf(vx, Ms[l0 * 64 + lane], y0);
            y1 = fmaf(vx, Ms[l0 * 64 + 32 + lane], y1);
            y0 = fmaf(vy, Ms[(l0 + 1) * 64 + lane], y0);
            y1 = fmaf(vy, Ms[(l0 + 1) * 64 + 32 + lane], y1);
        }
        size_t o = (size_t)row * NJ + colbase;
        store_split(o + lane, y0);
        store_split(o + 32 + lane, y1);
    }
}

// ---------------- decode: PERSISTENT col-panel kernel (2-pass fp16) -----------
// grid (40, 3). B panel 128 cols fp16 resident; stream 64-row A tiles (hi/lo).
// 256 threads, 8 warps 2Mx4N (warp 32x32).
// smem bytes (row stride 200 halves = 400B):
//   B@0 (51200) | A stage s @ 51200+s*51200: Ahi(25600)+Alo(25600)
#define DEC_SMEM_BYTES 153600
__global__ __launch_bounds__(256, 1) void decode_kernel(float* __restrict__ out) {
    extern __shared__ __half sm[];
    const uint32_t sbase = s2u(sm);
    const int tid = threadIdx.x, wid = tid >> 5, lane = tid & 31;
    const int col0 = blockIdx.x * 128;
    const int rowg = blockIdx.y;
    const int start = rowg * 85 + (rowg > 0 ? 1 : 0);
    const int count = (rowg == 0) ? 86 : 85;
    const int wm = (wid & 1) * 32, wn = (wid >> 1) * 32;

    // B panel load (once), fp16 single
    for (int i = tid; i < 3072; i += 256) {          // 128 rows x 24 chunks
        int n = i / 24, c = i - n * 24;
        uint32_t o = (uint32_t)(n * 200 + c * 8) * 2u;
        cp16(sbase + o, g_WdTH + (size_t)(col0 + n) * NJ + c * 8);
    }

    uint32_t a_off[6];
    int a_rel[6];
#pragma unroll
    for (int u = 0; u < 6; u++) {
        int i = tid + u * 256;
        int r = i / 24, c = i - r * 24;
        a_off[u] = (uint32_t)(r * 200 + c * 8) * 2u;
        a_rel[u] = r * NJ + c * 8;
    }
    auto cpA = [&](int tile, int s) {
        uint32_t base = sbase + 51200u + (uint32_t)s * 51200u;
        size_t g0 = (size_t)tile * 64 * NJ;
#pragma unroll
        for (int u = 0; u < 6; u++) {
            cp16(base + a_off[u],          g_Hhi + g0 + a_rel[u]);
            cp16(base + 25600u + a_off[u], g_Hlo + g0 + a_rel[u]);
        }
    };

    cpA(start, 0);
    cp_commit();

    float acc[2][4][4];
#pragma unroll 1
    for (int t = 0; t < count; t++) {
        const int s = t & 1;
        cp_wait<0>();
        __syncthreads();
        if (t + 1 < count) cpA(start + t + 1, s ^ 1);
        cp_commit();

#pragma unroll
        for (int i = 0; i < 2; i++)
#pragma unroll
            for (int j = 0; j < 4; j++)
#pragma unroll
                for (int k = 0; k < 4; k++) acc[i][j][k] = 0.f;

        const uint32_t abase = sbase + 51200u + (uint32_t)s * 51200u;
#pragma unroll
        for (int ks = 0; ks < 12; ks++) {
            const int kk = ks * 16;
            uint32_t ahi[2][4], alo[2][4];
#pragma unroll
            for (int mt = 0; mt < 2; mt++) {
                uint32_t o = (uint32_t)((wm + mt * 16 + (lane & 15)) * 200 +
                                        kk + (lane >> 4) * 8) * 2u;
                ldsm4(ahi[mt], abase + o);
                ldsm4(alo[mt], abase + 25600u + o);
            }
            uint32_t bhi[2][4];
#pragma unroll
            for (int pr = 0; pr < 2; pr++) {
                int n = wn + pr * 16 + (lane & 7) + ((lane >> 4) & 1) * 8;
                uint32_t o = (uint32_t)(n * 200 + kk + ((lane >> 3) & 1) * 8) * 2u;
                ldsm4(bhi[pr], sbase + o);
            }
#pragma unroll
            for (int mt = 0; mt < 2; mt++)
#pragma unroll
                for (int nt = 0; nt < 4; nt++) {
                    const uint32_t* bh = &bhi[nt >> 1][(nt & 1) * 2];
                    mma16816(acc[mt][nt], ahi[mt], bh);
                    mma16816(acc[mt][nt], alo[mt], bh);
                }
        }

        const int trow0 = (start + t) * 64;
#pragma unroll
        for (int mt = 0; mt < 2; mt++) {
            int r = trow0 + wm + mt * 16 + (lane >> 2);
#pragma unroll
            for (int nt = 0; nt < 4; nt++) {
                int cg = col0 + wn + nt * 8 + (lane & 3) * 2;
                if (cg < ND) {
                    *(float2*)(out + (size_t)r * ND + cg) =
                        make_float2(acc[mt][nt][0], acc[mt][nt][1]);
                    *(float2*)(out + (size_t)(r + 8) * ND + cg) =
                        make_float2(acc[mt][nt][2], acc[mt][nt][3]);
                }
            }
        }
    }
}

// ---------------- launch --------------------------------------------------------
extern "C" void kernel_launch(void* const* d_in, const int* in_sizes, int n_in,
                              void* d_out, int out_size) {
    const float* expr = (const float*)d_in[0];
    const int* sb = (const int*)d_in[1];
    const int* tb = (const int*)d_in[2];
    const int* sc = (const int*)d_in[3];
    const int* tc = (const int*)d_in[4];
    const float* Wb  = (const float*)d_in[5];
    const float* Web = (const float*)d_in[6];
    const float* Wdb = (const float*)d_in[7];
    const float* Whb = (const float*)d_in[8];
    const float* Wec = (const float*)d_in[9];
    const float* Wdc = (const float*)d_in[10];
    const float* Whc = (const float*)d_in[11];
    float* out = (float*)d_out;

    cudaFuncSetAttribute(encode_kernel, cudaFuncAttributeMaxDynamicSharedMemorySize,
                         ENC_SMEM_BYTES);
    cudaFuncSetAttribute(decode_kernel, cudaFuncAttributeMaxDynamicSharedMemorySize,
                         DEC_SMEM_BYTES);

    // Order keeps encode as the 4th launch (the one ncu captures).
    pack_enc_kernel<<<(NJ * KENC_PAD) / 256, 256>>>(Wb, Web, Wec);
    composite_kernel<<<NBIN, 256>>>(Whb, Whc);
    bucket_all_kernel<<<1, 1024>>>(sb, tb, sc, tc);
    encode_kernel<<<NB / 128, 512, ENC_SMEM_BYTES>>>(expr);
    heads_kernel<<<NBIN, 256>>>();
    pack_dec_kernel<<<(NDEC_PAD * NJ) / 256, 256>>>(Wb, Wdb, Wdc);
    decode_kernel<<<dim3(40, 3), 256, DEC_SMEM_BYTES>>>(out);
}

// round 10
// speedup vs baseline: 1.8474x; 1.2847x over previous
#include <cuda_runtime.h>
#include <cuda_fp16.h>
#include <cstdint>

#define NB 16384
#define ND 5000
#define NJ 192
#define KENC_PAD 5056          // 158 * 32
#define NDEC_PAD 5120          // 40 * 128
#define DEC_SCALE 0.0159f
#define CARD_B 24
#define CARD_C 10
#define NBIN (CARD_B * CARD_B + CARD_C * CARD_C)   // 676

// ---------------- device-global scratch --------------------------------------
__device__ __align__(16) float  g_H[NB * NJ];
__device__ __align__(16) __half g_Hh[NB * NJ];              // single fp16 H
__device__ __align__(16) __half g_WencH[NJ * KENC_PAD];     // fp16 enc weights
__device__ __align__(16) __half g_WdTH[NDEC_PAD * NJ];      // fp16 dec weights
__device__ __align__(16) float  g_MbT[CARD_B * CARD_B * 4096];
__device__ __align__(16) float  g_McT[CARD_C * CARD_C * 4096];
__device__ int g_off[NBIN + 1];
__device__ int g_rows[2 * NB];

// ---------------- PTX helpers -------------------------------------------------
__device__ __forceinline__ uint32_t s2u(const void* p) {
    return (uint32_t)__cvta_generic_to_shared(p);
}
__device__ __forceinline__ void cp16(uint32_t dst, const void* src) {
    asm volatile("cp.async.cg.shared.global [%0], [%1], 16;" :: "r"(dst), "l"(src));
}
__device__ __forceinline__ void cp_commit() {
    asm volatile("cp.async.commit_group;" ::: "memory");
}
template <int N> __device__ __forceinline__ void cp_wait() {
    asm volatile("cp.async.wait_group %0;" :: "n"(N) : "memory");
}
__device__ __forceinline__ void sts128(uint32_t a, uint32_t x, uint32_t y,
                                       uint32_t z, uint32_t w) {
    asm volatile("st.shared.v4.b32 [%0], {%1,%2,%3,%4};"
                 :: "r"(a), "r"(x), "r"(y), "r"(z), "r"(w) : "memory");
}
__device__ __forceinline__ void ldsm4(uint32_t* r, uint32_t a) {
    asm volatile("ldmatrix.sync.aligned.m8n8.x4.shared.b16 {%0,%1,%2,%3}, [%4];"
                 : "=r"(r[0]), "=r"(r[1]), "=r"(r[2]), "=r"(r[3]) : "r"(a));
}
__device__ __forceinline__ void mma16816(float* c, const uint32_t* a, const uint32_t* b) {
    asm volatile("mma.sync.aligned.m16n8k16.row.col.f32.f16.f16.f32 "
                 "{%0,%1,%2,%3},{%4,%5,%6,%7},{%8,%9},{%0,%1,%2,%3};"
                 : "+f"(c[0]), "+f"(c[1]), "+f"(c[2]), "+f"(c[3])
                 : "r"(a[0]), "r"(a[1]), "r"(a[2]), "r"(a[3]), "r"(b[0]), "r"(b[1]));
}
__device__ __forceinline__ uint32_t pack2h(float f0, float f1) {
    __half2 h = __floats2half2_rn(f0, f1);
    return *(uint32_t*)&h;
}

// ---------------- pack kernels ------------------------------------------------
__global__ void pack_enc_kernel(const float* __restrict__ Wb,
                                const float* __restrict__ Web,
                                const float* __restrict__ Wec) {
    int idx = blockIdx.x * blockDim.x + threadIdx.x;
    int j = idx / KENC_PAD, d = idx - j * KENC_PAD;
    float v = 0.f;
    if (d < ND) {
        if (j < 64)       v = Wb[j * ND + d];
        else if (j < 128) v = Web[(j - 64) * ND + d];
        else              v = Wec[(j - 128) * ND + d];
    }
    g_WencH[idx] = __float2half_rn(v);
}
__global__ void pack_dec_kernel(const float* __restrict__ Wb,
                                const float* __restrict__ Wdb,
                                const float* __restrict__ Wdc) {
    int idx = blockIdx.x * blockDim.x + threadIdx.x;
    int n = idx / NJ, j = idx - n * NJ;
    float v = 0.f;
    if (n < ND) {
        if (j < 64)       v = Wb[j * ND + n];
        else if (j < 128) v = Wdb[n * 64 + (j - 64)];
        else              v = Wdc[n * 64 + (j - 128)];
    }
    g_WdTH[idx] = __float2half_rn(v);
}

// ---------------- composite: MT[pair][l][m] = scale * (W[t] @ W[s])[m,l] -----
__global__ __launch_bounds__(256) void composite_kernel(const float* __restrict__ Whb,
                                                        const float* __restrict__ Whc) {
    __shared__ float sT[4096], sS[4096];
    int pair = blockIdx.x;
    const float *Wt, *Ws;
    float* out;
    if (pair < CARD_B * CARD_B) {
        Wt = Whb + (size_t)(pair / CARD_B) * 4096;
        Ws = Whb + (size_t)(pair % CARD_B) * 4096;
        out = g_MbT + (size_t)pair * 4096;
    } else {
        int p = pair - CARD_B * CARD_B;
        Wt = Whc + (size_t)(p / CARD_C) * 4096;
        Ws = Whc + (size_t)(p % CARD_C) * 4096;
        out = g_McT + (size_t)p * 4096;
    }
    int tid = threadIdx.x;
    for (int i = tid; i < 4096; i += 256) { sT[i] = Wt[i]; sS[i] = Ws[i]; }
    __syncthreads();
    int m = tid >> 2, n0 = (tid & 3) * 16;
    float c[16];
#pragma unroll
    for (int j = 0; j < 16; j++) c[j] = 0.f;
    for (int l = 0; l < 64; l++) {
        float a = sT[m * 64 + l];
#pragma unroll
        for (int j = 0; j < 16; j++) c[j] = fmaf(a, sS[l * 64 + n0 + j], c[j]);
    }
#pragma unroll
    for (int j = 0; j < 16; j++) out[(n0 + j) * 64 + m] = c[j] * DEC_SCALE;
}

// ---------------- bucketing: single-CTA fused count/scan/scatter --------------
__global__ __launch_bounds__(1024) void bucket_all_kernel(const int* __restrict__ sb,
                                                          const int* __restrict__ tb,
                                                          const int* __restrict__ sc,
                                                          const int* __restrict__ tc) {
    __shared__ int scnt[NBIN];
    __shared__ int scur[NBIN];
    const int tid = threadIdx.x;
    for (int i = tid; i < NBIN; i += 1024) scnt[i] = 0;
    __syncthreads();
    for (int row = tid; row < NB; row += 1024) {
        atomicAdd(&scnt[tb[row] * CARD_B + sb[row]], 1);
        atomicAdd(&scnt[CARD_B * CARD_B + tc[row] * CARD_C + sc[row]], 1);
    }
    __syncthreads();
    if (tid == 0) {
        int acc = 0;
        for (int i = 0; i < NBIN; i++) {
            scur[i] = acc;
            g_off[i] = acc;
            acc += scnt[i];
        }
        g_off[NBIN] = acc;
    }
    __syncthreads();
    for (int row = tid; row < NB; row += 1024) {
        int pb = tb[row] * CARD_B + sb[row];
        int pc = CARD_B * CARD_B + tc[row] * CARD_C + sc[row];
        g_rows[atomicAdd(&scur[pb], 1)] = row;
        g_rows[atomicAdd(&scur[pc], 1)] = row;
    }
}

// ---------------- encode: single-pass fp16 ------------------------------------
// 512 threads, 16 warps 4Mx4N (warp 32x48). Tile 128x192, BK=32, double-buffered.
// Stage bytes: A@0 (10240) | B@10240 (15360) ; 25600/stage.
#define ENC_SMEM_BYTES (2 * 25600)
__global__ __launch_bounds__(512, 1) void encode_kernel(const float* __restrict__ A) {
    extern __shared__ __half sm[];
    const uint32_t sbase = s2u(sm);
    const int tid = threadIdx.x, wid = tid >> 5, lane = tid & 31;
    const int row0 = blockIdx.x * 128;
    const int wm = (wid & 3) * 32, wn = (wid >> 2) * 48;

    float acc[2][6][4];
#pragma unroll
    for (int i = 0; i < 2; i++)
#pragma unroll
        for (int j = 0; j < 6; j++)
#pragma unroll
            for (int k = 0; k < 4; k++) acc[i][j][k] = 0.f;

    float4 av0, av1;
    const int r_a = tid >> 2, c_a = tid & 3;
    auto ldgA = [&](int kt) {
        const int kg = kt * 32 + c_a * 8;
        if (kg < ND) {
            const float4* p = (const float4*)(A + (size_t)(row0 + r_a) * ND + kg);
            av0 = p[0]; av1 = p[1];
        } else {
            av0 = make_float4(0.f, 0.f, 0.f, 0.f);
            av1 = av0;
        }
    };
    auto stsA = [&](int s) {
        uint32_t base = sbase + (uint32_t)s * 25600u;
        uint32_t o = (uint32_t)(r_a * 40 + c_a * 8) * 2u;
        sts128(base + o, pack2h(av0.x, av0.y), pack2h(av0.z, av0.w),
                         pack2h(av1.x, av1.y), pack2h(av1.z, av1.w));
    };
    auto cpB = [&](int kt, int s) {
        const int k0 = kt * 32;
        uint32_t base = sbase + (uint32_t)s * 25600u;
        {
            int n = tid >> 2, c = tid & 3;
            uint32_t o = (uint32_t)(n * 40 + c * 8) * 2u;
            cp16(base + 10240u + o, g_WencH + (size_t)n * KENC_PAD + k0 + c * 8);
        }
        if (tid < 256) {
            int idx = tid + 512;
            int n = idx >> 2, c = idx & 3;
            uint32_t o = (uint32_t)(n * 40 + c * 8) * 2u;
            cp16(base + 10240u + o, g_WencH + (size_t)n * KENC_PAD + k0 + c * 8);
        }
    };

    const int NT = KENC_PAD / 32;   // 158
    ldgA(0);
    cpB(0, 0);
    cp_commit();
#pragma unroll 1
    for (int kt = 0; kt < NT; kt++) {
        const int s = kt & 1;
        stsA(s);
        cp_wait<0>();
        __syncthreads();
        if (kt + 1 < NT) {
            ldgA(kt + 1);
            cpB(kt + 1, s ^ 1);
            cp_commit();
        }
        const uint32_t base = sbase + (uint32_t)s * 25600u;
#pragma unroll
        for (int ks = 0; ks < 2; ks++) {
            const int kk = ks * 16;
            uint32_t ah[2][4];
#pragma unroll
            for (int mt = 0; mt < 2; mt++) {
                uint32_t o = (uint32_t)((wm + mt * 16 + (lane & 15)) * 40 +
                                        kk + (lane >> 4) * 8) * 2u;
                ldsm4(ah[mt], base + o);
            }
            uint32_t bh[3][4];
#pragma unroll
            for (int pr = 0; pr < 3; pr++) {
                int n = wn + pr * 16 + (lane & 7) + ((lane >> 4) & 1) * 8;
                uint32_t o = (uint32_t)(n * 40 + kk + ((lane >> 3) & 1) * 8) * 2u;
                ldsm4(bh[pr], base + 10240u + o);
            }
#pragma unroll
            for (int mt = 0; mt < 2; mt++)
#pragma unroll
                for (int nt = 0; nt < 6; nt++)
                    mma16816(acc[mt][nt], ah[mt], &bh[nt >> 1][(nt & 1) * 2]);
        }
    }

    // epilogue -> g_H fp32 (+ fp16 for base cols < 64)
#pragma unroll
    for (int mt = 0; mt < 2; mt++) {
        int r = row0 + wm + mt * 16 + (lane >> 2);
#pragma unroll
        for (int nt = 0; nt < 6; nt++) {
            int cg = wn + nt * 8 + (lane & 3) * 2;
#pragma unroll
            for (int half = 0; half < 2; half++) {
                int rr = r + half * 8;
                float v0 = acc[mt][nt][half * 2], v1 = acc[mt][nt][half * 2 + 1];
                *(float2*)(g_H + (size_t)rr * NJ + cg) = make_float2(v0, v1);
                if (cg < 64)
                    *(uint32_t*)(g_Hh + (size_t)rr * NJ + cg) = pack2h(v0, v1);
            }
        }
    }
}

// ---------------- heads: one CTA per context pair ----------------------------
__global__ __launch_bounds__(256) void heads_kernel() {
    __shared__ float Ms[4096];
    const int pair = blockIdx.x;
    const int tid = threadIdx.x, wid = tid >> 5, lane = tid & 31;
    const float* M = (pair < CARD_B * CARD_B)
                         ? g_MbT + (size_t)pair * 4096
                         : g_McT + (size_t)(pair - CARD_B * CARD_B) * 4096;
    const int colbase = (pair < CARD_B * CARD_B) ? 64 : 128;
    for (int i = tid; i < 4096; i += 256) Ms[i] = M[i];
    __syncthreads();
    const int off = g_off[pair], cnt = g_off[pair + 1] - off;
    for (int i = wid; i < cnt; i += 8) {
        int row = g_rows[off + i];
        float2 x = *(const float2*)(g_H + (size_t)row * NJ + colbase + lane * 2);
        float y0 = 0.f, y1 = 0.f;
#pragma unroll
        for (int li = 0; li < 32; li++) {
            float vx = __shfl_sync(0xffffffffu, x.x, li);
            float vy = __shfl_sync(0xffffffffu, x.y, li);
            int l0 = li * 2;
            y0 = fmaf(vx, Ms[l0 * 64 + lane], y0);
            y1 = fmaf(vx, Ms[l0 * 64 + 32 + lane], y1);
            y0 = fmaf(vy, Ms[(l0 + 1) * 64 + lane], y0);
            y1 = fmaf(vy, Ms[(l0 + 1) * 64 + 32 + lane], y1);
        }
        size_t o = (size_t)row * NJ + colbase;
        g_Hh[o + lane]      = __float2half_rn(y0);
        g_Hh[o + 32 + lane] = __float2half_rn(y1);
    }
}

// ---------------- decode: PERSISTENT col-panel kernel (single-pass fp16) ------
// grid (40, 3). B panel 128 cols fp16 resident; stream 64-row fp16 A tiles.
// 256 threads, 8 warps 2Mx4N (warp 32x32).
// smem bytes (row stride 200 halves = 400B):
//   B@0 (51200) | A stage s @ 51200 + s*25600 (25600 each)
#define DEC_SMEM_BYTES (51200 + 2 * 25600)
__global__ __launch_bounds__(256, 1) void decode_kernel(float* __restrict__ out) {
    extern __shared__ __half sm[];
    const uint32_t sbase = s2u(sm);
    const int tid = threadIdx.x, wid = tid >> 5, lane = tid & 31;
    const int col0 = blockIdx.x * 128;
    const int rowg = blockIdx.y;
    const int start = rowg * 85 + (rowg > 0 ? 1 : 0);
    const int count = (rowg == 0) ? 86 : 85;
    const int wm = (wid & 1) * 32, wn = (wid >> 1) * 32;

    // B panel load (once), fp16 single
    for (int i = tid; i < 3072; i += 256) {          // 128 rows x 24 chunks
        int n = i / 24, c = i - n * 24;
        uint32_t o = (uint32_t)(n * 200 + c * 8) * 2u;
        cp16(sbase + o, g_WdTH + (size_t)(col0 + n) * NJ + c * 8);
    }

    uint32_t a_off[6];
    int a_rel[6];
#pragma unroll
    for (int u = 0; u < 6; u++) {
        int i = tid + u * 256;
        int r = i / 24, c = i - r * 24;
        a_off[u] = (uint32_t)(r * 200 + c * 8) * 2u;
        a_rel[u] = r * NJ + c * 8;
    }
    auto cpA = [&](int tile, int s) {
        uint32_t base = sbase + 51200u + (uint32_t)s * 25600u;
        size_t g0 = (size_t)tile * 64 * NJ;
#pragma unroll
        for (int u = 0; u < 6; u++)
            cp16(base + a_off[u], g_Hh + g0 + a_rel[u]);
    };

    cpA(start, 0);
    cp_commit();

    float acc[2][4][4];
#pragma unroll 1
    for (int t = 0; t < count; t++) {
        const int s = t & 1;
        cp_wait<0>();
        __syncthreads();
        if (t + 1 < count) cpA(start + t + 1, s ^ 1);
        cp_commit();

#pragma unroll
        for (int i = 0; i < 2; i++)
#pragma unroll
            for (int j = 0; j < 4; j++)
#pragma unroll
                for (int k = 0; k < 4; k++) acc[i][j][k] = 0.f;

        const uint32_t abase = sbase + 51200u + (uint32_t)s * 25600u;
#pragma unroll
        for (int ks = 0; ks < 12; ks++) {
            const int kk = ks * 16;
            uint32_t ah[2][4];
#pragma unroll
            for (int mt = 0; mt < 2; mt++) {
                uint32_t o = (uint32_t)((wm + mt * 16 + (lane & 15)) * 200 +
                                        kk + (lane >> 4) * 8) * 2u;
                ldsm4(ah[mt], abase + o);
            }
            uint32_t bh[2][4];
#pragma unroll
            for (int pr = 0; pr < 2; pr++) {
                int n = wn + pr * 16 + (lane & 7) + ((lane >> 4) & 1) * 8;
                uint32_t o = (uint32_t)(n * 200 + kk + ((lane >> 3) & 1) * 8) * 2u;
                ldsm4(bh[pr], sbase + o);
            }
#pragma unroll
            for (int mt = 0; mt < 2; mt++)
#pragma unroll
                for (int nt = 0; nt < 4; nt++)
                    mma16816(acc[mt][nt], ah[mt], &bh[nt >> 1][(nt & 1) * 2]);
        }

        const int trow0 = (start + t) * 64;
#pragma unroll
        for (int mt = 0; mt < 2; mt++) {
            int r = trow0 + wm + mt * 16 + (lane >> 2);
#pragma unroll
            for (int nt = 0; nt < 4; nt++) {
                int cg = col0 + wn + nt * 8 + (lane & 3) * 2;
                if (cg < ND) {
                    *(float2*)(out + (size_t)r * ND + cg) =
                        make_float2(acc[mt][nt][0], acc[mt][nt][1]);
                    *(float2*)(out + (size_t)(r + 8) * ND + cg) =
                        make_float2(acc[mt][nt][2], acc[mt][nt][3]);
                }
            }
        }
    }
}

// ---------------- launch --------------------------------------------------------
extern "C" void kernel_launch(void* const* d_in, const int* in_sizes, int n_in,
                              void* d_out, int out_size) {
    const float* expr = (const float*)d_in[0];
    const int* sb = (const int*)d_in[1];
    const int* tb = (const int*)d_in[2];
    const int* sc = (const int*)d_in[3];
    const int* tc = (const int*)d_in[4];
    const float* Wb  = (const float*)d_in[5];
    const float* Web = (const float*)d_in[6];
    const float* Wdb = (const float*)d_in[7];
    const float* Whb = (const float*)d_in[8];
    const float* Wec = (const float*)d_in[9];
    const float* Wdc = (const float*)d_in[10];
    const float* Whc = (const float*)d_in[11];
    float* out = (float*)d_out;

    cudaFuncSetAttribute(encode_kernel, cudaFuncAttributeMaxDynamicSharedMemorySize,
                         ENC_SMEM_BYTES);
    cudaFuncSetAttribute(decode_kernel, cudaFuncAttributeMaxDynamicSharedMemorySize,
                         DEC_SMEM_BYTES);

    // Order keeps encode as the 4th launch (the one ncu captures).
    pack_enc_kernel<<<(NJ * KENC_PAD) / 256, 256>>>(Wb, Web, Wec);
    composite_kernel<<<NBIN, 256>>>(Whb, Whc);
    bucket_all_kernel<<<1, 1024>>>(sb, tb, sc, tc);
    encode_kernel<<<NB / 128, 512, ENC_SMEM_BYTES>>>(expr);
    heads_kernel<<<NBIN, 256>>>();
    pack_dec_kernel<<<(NDEC_PAD * NJ) / 256, 256>>>(Wb, Wdb, Wdc);
    decode_kernel<<<dim3(40, 3), 256, DEC_SMEM_BYTES>>>(out);
}